// round 16
// baseline (speedup 1.0000x reference)
#include <cuda_runtime.h>
#include <cuda_fp16.h>

#define IN_DIM 128
#define HIDD   128
#define OUTD   40
#define MAXN   50000
#define MAXE   800000
#define NB_FUSED 296   // 2 blocks/SM on 148 SMs: guaranteed co-resident

// ---------------- scratch (device globals: allocation-free) ----------------
static __device__ __half g_ywh[MAXN * HIDD];  // fp16: (x @ W1), unscaled
static __device__ __align__(16) __half g_hh[MAXN * HIDD]; // fp16 layer-1 out
static __device__ __half g_owh[MAXN * OUTD];  // fp16: dinv * (h @ W2)
static __device__ int    g_degi[MAXN];
static __device__ float  g_dinv[MAXN];
static __device__ int    g_rs  [MAXN + 1];
static __device__ int    g_cur [MAXN];
static __device__ int    g_col [MAXE];
static __device__ int    g_bsum[NB_FUSED];
static __device__ unsigned g_bar_count;       // load-time 0; self-cleaning
static __device__ unsigned g_bar_gen;         // monotonic

// ---------------- helpers ----------------
__device__ __forceinline__ int detect_is64_warp(const int* __restrict__ ei32) {
    int lane = threadIdx.x & 31;
    int v = ei32[1 + 2 * lane];
    unsigned any = __ballot_sync(0xffffffffu, v != 0);
    return any == 0 ? 1 : 0;
}

__device__ __forceinline__ int get_idx(const void* ei, long long pos, int is64) {
    return is64 ? (int)((const long long*)ei)[pos] : ((const int*)ei)[pos];
}

__device__ __forceinline__ unsigned pack_h2(float a, float b) {
    __half2 h = __floats2half2_rn(a, b);
    return *(unsigned*)&h;
}

__device__ __forceinline__ void grid_barrier() {
    __syncthreads();
    if (threadIdx.x == 0) {
        __threadfence();
        unsigned gen = *(volatile unsigned*)&g_bar_gen;
        if (atomicAdd(&g_bar_count, 1u) == (unsigned)gridDim.x - 1u) {
            g_bar_count = 0;
            __threadfence();
            *(volatile unsigned*)&g_bar_gen = gen + 1u;
        } else {
            while (*(volatile unsigned*)&g_bar_gen == gen) __nanosleep(64);
        }
        __threadfence();
    }
    __syncthreads();
}

// ---------------- fused CSR build: deg -> scan -> rs/dinv -> scatter --------
__global__ void __launch_bounds__(256) csr_fused_kernel(const void* __restrict__ ei,
                                                        int N, int E, int nbScan) {
    const int tid = threadIdx.x;
    const int bid = blockIdx.x;
    const int lane = tid & 31, wid = tid >> 5;
    const int is64 = detect_is64_warp((const int*)ei);
    const int stride = gridDim.x * 256;

    for (int e = bid * 256 + tid; e < E; e += stride) {
        int d = get_idx(ei, (long long)E + e, is64);
        atomicAdd(&g_degi[d], 1);
    }
    grid_barrier();

    if (bid < nbScan) {
        int i = bid * 256 + tid;
        int v = (i < N) ? g_degi[i] : 0;
#pragma unroll
        for (int o = 16; o > 0; o >>= 1) v += __shfl_xor_sync(0xffffffffu, v, o);
        __shared__ int ps[8];
        if (lane == 0) ps[wid] = v;
        __syncthreads();
        if (tid == 0) {
            int s = 0;
#pragma unroll
            for (int w = 0; w < 8; w++) s += ps[w];
            g_bsum[bid] = s;
        }
    }
    grid_barrier();

    if (bid == 0) {
        int v = (tid < nbScan) ? g_bsum[tid] : 0;
        __shared__ int ws2[32];
        if (tid < 32) ws2[tid] = 0;
        __syncthreads();
        int x = v;
#pragma unroll
        for (int o = 1; o < 32; o <<= 1) {
            int u = __shfl_up_sync(0xffffffffu, x, o);
            if (lane >= o) x += u;
        }
        if (lane == 31) ws2[wid] = x;
        __syncthreads();
        if (wid == 0) {
            int w = ws2[lane];
#pragma unroll
            for (int o = 1; o < 32; o <<= 1) {
                int u = __shfl_up_sync(0xffffffffu, w, o);
                if (lane >= o) w += u;
            }
            ws2[lane] = w;
        }
        __syncthreads();
        int excl = x - v + (wid > 0 ? ws2[wid - 1] : 0);
        if (tid < nbScan) g_bsum[tid] = excl;
    }
    grid_barrier();

    if (bid < nbScan) {
        int i = bid * 256 + tid;
        int v = (i < N) ? g_degi[i] : 0;
        __shared__ int ws3[32];
        if (tid < 32) ws3[tid] = 0;
        __syncthreads();
        int x = v;
#pragma unroll
        for (int o = 1; o < 32; o <<= 1) {
            int u = __shfl_up_sync(0xffffffffu, x, o);
            if (lane >= o) x += u;
        }
        if (lane == 31) ws3[wid] = x;
        __syncthreads();
        if (wid == 0) {
            int w = ws3[lane];
#pragma unroll
            for (int o = 1; o < 32; o <<= 1) {
                int u = __shfl_up_sync(0xffffffffu, w, o);
                if (lane >= o) w += u;
            }
            ws3[lane] = w;
        }
        __syncthreads();
        int excl = x - v + (wid > 0 ? ws3[wid - 1] : 0) + g_bsum[bid];
        if (i < N) {
            g_rs[i]   = excl;
            g_cur[i]  = excl;
            g_dinv[i] = rsqrtf((float)(v + 1));
            g_degi[i] = 0;
        }
        if (i == 0) g_rs[N] = E;
    }
    grid_barrier();

    for (int e = bid * 256 + tid; e < E; e += stride) {
        int s = get_idx(ei, e, is64);
        int d = get_idx(ei, (long long)E + e, is64);
        int pos = atomicAdd(&g_cur[d], 1);
        g_col[pos] = s;
    }
}

// ---------------- FP16 GEMM1 (256 thr, 8 warps x [32 rows x 64 cols]) -------
#define G1_LDA 68
#define G1_LDB 136
#define G1_SMEM ((128 * G1_LDA + 64 * G1_LDB) * 4)

__global__ void __launch_bounds__(256, 2) gemm1_tc_kernel(const float* __restrict__ A,
                                                          const float* __restrict__ B,
                                                          __half* __restrict__ C, int M) {
    extern __shared__ unsigned sm1[];
    unsigned* As = sm1;
    unsigned* Bs = sm1 + 128 * G1_LDA;

    const int tid  = threadIdx.x;
    const int wid  = tid >> 5;
    const int lane = tid & 31;
    const int g    = lane >> 2;
    const int t    = lane & 3;
    const int wr   = wid & 3;
    const int wn   = wid >> 2;
    const int row0 = blockIdx.x * 128;

    for (int idx = tid; idx < 64 * 128; idx += 256) {
        int kw = idx >> 7, n = idx & 127;
        Bs[kw * G1_LDB + n] = pack_h2(B[(size_t)(2 * kw) * 128 + n],
                                      B[(size_t)(2 * kw + 1) * 128 + n]);
    }
#pragma unroll
    for (int f = 0; f < 16; f++) {
        int l4  = tid + f * 256;
        int row = l4 >> 5;
        int fq  = l4 & 31;
        float4 v = make_float4(0.f, 0.f, 0.f, 0.f);
        if (row0 + row < M)
            v = *(const float4*)(A + (size_t)(row0 + row) * 128 + fq * 4);
        As[row * G1_LDA + fq * 2    ] = pack_h2(v.x, v.y);
        As[row * G1_LDA + fq * 2 + 1] = pack_h2(v.z, v.w);
    }
    __syncthreads();

    float c[2][8][4];
#pragma unroll
    for (int mi = 0; mi < 2; mi++)
#pragma unroll
        for (int j = 0; j < 8; j++)
#pragma unroll
            for (int q = 0; q < 4; q++) c[mi][j][q] = 0.0f;

#pragma unroll
    for (int kh = 0; kh < 8; kh++) {
        unsigned a[2][4];
#pragma unroll
        for (int mi = 0; mi < 2; mi++) {
            int R = wr * 32 + mi * 16;
            a[mi][0] = As[(R + g    ) * G1_LDA + kh * 8 + t    ];
            a[mi][1] = As[(R + 8 + g) * G1_LDA + kh * 8 + t    ];
            a[mi][2] = As[(R + g    ) * G1_LDA + kh * 8 + t + 4];
            a[mi][3] = As[(R + 8 + g) * G1_LDA + kh * 8 + t + 4];
        }
#pragma unroll
        for (int j = 0; j < 8; j++) {
            int n = wn * 64 + j * 8 + g;
            unsigned b0 = Bs[(kh * 8 + t    ) * G1_LDB + n];
            unsigned b1 = Bs[(kh * 8 + t + 4) * G1_LDB + n];
#pragma unroll
            for (int mi = 0; mi < 2; mi++) {
                asm volatile(
                    "mma.sync.aligned.m16n8k16.row.col.f32.f16.f16.f32 "
                    "{%0,%1,%2,%3}, {%4,%5,%6,%7}, {%8,%9}, {%0,%1,%2,%3};"
                    : "+f"(c[mi][j][0]), "+f"(c[mi][j][1]),
                      "+f"(c[mi][j][2]), "+f"(c[mi][j][3])
                    : "r"(a[mi][0]), "r"(a[mi][1]), "r"(a[mi][2]), "r"(a[mi][3]),
                      "r"(b0), "r"(b1));
            }
        }
    }

#pragma unroll
    for (int mi = 0; mi < 2; mi++) {
        int r1 = row0 + wr * 32 + mi * 16 + g;
        int r2 = r1 + 8;
#pragma unroll
        for (int j = 0; j < 8; j++) {
            int n = wn * 64 + j * 8 + t * 2;
            if (r1 < M)
                *(__half2*)(C + (size_t)r1 * 128 + n) =
                    __floats2half2_rn(c[mi][j][0], c[mi][j][1]);
            if (r2 < M)
                *(__half2*)(C + (size_t)r2 * 128 + n) =
                    __floats2half2_rn(c[mi][j][2], c[mi][j][3]);
        }
    }
}

// ---------------- fused tail: agg1 -> gemm2 -> agg2 (persistent, 296 blocks)
#define G2_LDA 68
#define G2_LDB 40

__global__ void __launch_bounds__(256, 2) tail_fused_kernel(const float* __restrict__ b1,
                                                            const float* __restrict__ W2,
                                                            const float* __restrict__ b2,
                                                            float* __restrict__ out, int N) {
    __shared__ unsigned As[128 * G2_LDA];   // 34.8 KB
    __shared__ unsigned Bs[64 * G2_LDB];    // 10.2 KB

    const int tid  = threadIdx.x;
    const int bid  = blockIdx.x;
    const int wid  = tid >> 5;
    const int lane = tid & 31;
    const int g    = lane >> 2;
    const int t    = lane & 3;
    const int gw   = bid * 8 + wid;        // global warp id
    const int nw   = gridDim.x * 8;        // total warps

    // stage W2 once (smem idle during agg1 phase)
    for (int idx = tid; idx < 64 * OUTD; idx += 256) {
        int kw = idx / OUTD, n = idx - kw * OUTD;
        Bs[kw * G2_LDB + n] = pack_h2(W2[(size_t)(2 * kw) * OUTD + n],
                                      W2[(size_t)(2 * kw + 1) * OUTD + n]);
    }

    // ---- Phase 1: agg1 (warp per node, grid-stride) ----
    for (int d = gw; d < N; d += nw) {
        const __half* __restrict__ yw = g_ywh;
        float di = g_dinv[d];
        uint2 u = *(const uint2*)(yw + (size_t)d * 128 + lane * 4);
        float2 f0 = __half22float2(*(__half2*)&u.x);
        float2 f1 = __half22float2(*(__half2*)&u.y);
        float4 acc = make_float4(f0.x * di, f0.y * di, f1.x * di, f1.y * di);

        int s0 = g_rs[d], s1 = g_rs[d + 1];
        for (int base = s0; base < s1; base += 32) {
            int n = s1 - base; if (n > 32) n = 32;
            int c = (lane < n) ? g_col[base + lane] : 0;
            float dv = (lane < n) ? g_dinv[c] : 0.0f;
#pragma unroll 4
            for (int j = 0; j < n; j++) {
                int s = __shfl_sync(0xffffffffu, c, j);
                float w = __shfl_sync(0xffffffffu, dv, j);
                uint2 v = *(const uint2*)(yw + (size_t)s * 128 + lane * 4);
                float2 a = __half22float2(*(__half2*)&v.x);
                float2 b = __half22float2(*(__half2*)&v.y);
                acc.x = fmaf(a.x, w, acc.x);
                acc.y = fmaf(a.y, w, acc.y);
                acc.z = fmaf(b.x, w, acc.z);
                acc.w = fmaf(b.y, w, acc.w);
            }
        }
        float4 bb = *(const float4*)(b1 + lane * 4);
        uint2 st;
        st.x = pack_h2(fmaxf(acc.x * di + bb.x, 0.0f), fmaxf(acc.y * di + bb.y, 0.0f));
        st.y = pack_h2(fmaxf(acc.z * di + bb.z, 0.0f), fmaxf(acc.w * di + bb.w, 0.0f));
        *(uint2*)(g_hh + (size_t)d * 128 + lane * 4) = st;
    }
    grid_barrier();

    // ---- Phase 2: gemm2 tiles (BM=128, 8 warps x [16 rows x 40 cols]) ----
    int nt = (N + 127) / 128;
    for (int tile = bid; tile < nt; tile += gridDim.x) {
        int row0 = tile * 128;
        __syncthreads();                     // protect As reuse
#pragma unroll
        for (int f = 0; f < 8; f++) {
            int idx = tid + f * 256;         // 2048 uint4
            int row = idx >> 4;
            int c4  = idx & 15;
            uint4 v = make_uint4(0u, 0u, 0u, 0u);
            if (row0 + row < N)
                v = *(const uint4*)(g_hh + (size_t)(row0 + row) * 128 + c4 * 8);
            *(uint4*)(As + row * G2_LDA + c4 * 4) = v;
        }
        __syncthreads();

        float c[5][4];
#pragma unroll
        for (int j = 0; j < 5; j++)
#pragma unroll
            for (int q = 0; q < 4; q++) c[j][q] = 0.0f;

#pragma unroll
        for (int kh = 0; kh < 8; kh++) {
            int R = wid * 16;
            unsigned a0 = As[(R + g    ) * G2_LDA + kh * 8 + t    ];
            unsigned a1 = As[(R + 8 + g) * G2_LDA + kh * 8 + t    ];
            unsigned a2 = As[(R + g    ) * G2_LDA + kh * 8 + t + 4];
            unsigned a3 = As[(R + 8 + g) * G2_LDA + kh * 8 + t + 4];
#pragma unroll
            for (int j = 0; j < 5; j++) {
                int n = j * 8 + g;
                unsigned b0 = Bs[(kh * 8 + t    ) * G2_LDB + n];
                unsigned b1 = Bs[(kh * 8 + t + 4) * G2_LDB + n];
                asm volatile(
                    "mma.sync.aligned.m16n8k16.row.col.f32.f16.f16.f32 "
                    "{%0,%1,%2,%3}, {%4,%5,%6,%7}, {%8,%9}, {%0,%1,%2,%3};"
                    : "+f"(c[j][0]), "+f"(c[j][1]), "+f"(c[j][2]), "+f"(c[j][3])
                    : "r"(a0), "r"(a1), "r"(a2), "r"(a3), "r"(b0), "r"(b1));
            }
        }

        int r1 = row0 + wid * 16 + g;
        int r2 = r1 + 8;
        float d1 = (r1 < N) ? g_dinv[r1] : 0.0f;
        float d2 = (r2 < N) ? g_dinv[r2] : 0.0f;
#pragma unroll
        for (int j = 0; j < 5; j++) {
            int n = j * 8 + t * 2;
            if (r1 < N)
                *(__half2*)(g_owh + (size_t)r1 * OUTD + n) =
                    __floats2half2_rn(c[j][0] * d1, c[j][1] * d1);
            if (r2 < N)
                *(__half2*)(g_owh + (size_t)r2 * OUTD + n) =
                    __floats2half2_rn(c[j][2] * d2, c[j][3] * d2);
        }
    }
    grid_barrier();

    // ---- Phase 3: agg2 (warp per node, dual-neighbor lanes) ----
    for (int d = gw; d < N; d += nw) {
        const __half* __restrict__ ow = g_owh;
        int grp = lane >> 4;
        int sub = lane & 15;
        bool act = (sub < 10);

        float4 acc = make_float4(0.f, 0.f, 0.f, 0.f);
        if (lane < 10) {
            uint2 u = *(const uint2*)(ow + (size_t)d * OUTD + lane * 4);
            float2 f0 = __half22float2(*(__half2*)&u.x);
            float2 f1 = __half22float2(*(__half2*)&u.y);
            acc = make_float4(f0.x, f0.y, f1.x, f1.y);
        }

        int s0 = g_rs[d], s1 = g_rs[d + 1];
        for (int base = s0; base < s1; base += 32) {
            int n = s1 - base; if (n > 32) n = 32;
            int c = (lane < n) ? g_col[base + lane] : 0;
            for (int j = 0; j < n; j += 2) {
                int idx = j + grp;
                int s = __shfl_sync(0xffffffffu, c, idx & 31);
                if (act && idx < n) {
                    uint2 v = *(const uint2*)(ow + (size_t)s * OUTD + sub * 4);
                    float2 a = __half22float2(*(__half2*)&v.x);
                    float2 b = __half22float2(*(__half2*)&v.y);
                    acc.x += a.x; acc.y += a.y; acc.z += b.x; acc.w += b.y;
                }
            }
        }

        acc.x += __shfl_xor_sync(0xffffffffu, acc.x, 16);
        acc.y += __shfl_xor_sync(0xffffffffu, acc.y, 16);
        acc.z += __shfl_xor_sync(0xffffffffu, acc.z, 16);
        acc.w += __shfl_xor_sync(0xffffffffu, acc.w, 16);

        float di = g_dinv[d];
        float4 l = make_float4(-1e30f, -1e30f, -1e30f, -1e30f);
        if (lane < 10) {
            float4 bb = *(const float4*)(b2 + lane * 4);
            l.x = acc.x * di + bb.x;
            l.y = acc.y * di + bb.y;
            l.z = acc.z * di + bb.z;
            l.w = acc.w * di + bb.w;
        }
        float m = fmaxf(fmaxf(l.x, l.y), fmaxf(l.z, l.w));
#pragma unroll
        for (int o = 16; o > 0; o >>= 1)
            m = fmaxf(m, __shfl_xor_sync(0xffffffffu, m, o));
        float4 e;
        e.x = __expf(l.x - m); e.y = __expf(l.y - m);
        e.z = __expf(l.z - m); e.w = __expf(l.w - m);
        float s = (lane < 10) ? (e.x + e.y + e.z + e.w) : 0.0f;
#pragma unroll
        for (int o = 16; o > 0; o >>= 1)
            s += __shfl_xor_sync(0xffffffffu, s, o);
        float inv = 1.0f / s;
        if (lane < 10) {
            float4 w;
            w.x = e.x * inv; w.y = e.y * inv; w.z = e.z * inv; w.w = e.w * inv;
            *(float4*)(out + (size_t)d * OUTD + lane * 4) = w;
        }
    }
}

// ---------------- launch (csr_fused || gemm1, then fused tail) --------------
extern "C" void kernel_launch(void* const* d_in, const int* in_sizes, int n_in,
                              void* d_out, int out_size) {
    const float* x  = (const float*)d_in[0];
    const void*  ei = d_in[1];
    const float* W1 = (const float*)d_in[2];
    const float* b1 = (const float*)d_in[3];
    const float* W2 = (const float*)d_in[4];
    const float* b2 = (const float*)d_in[5];
    float* out = (float*)d_out;

    int N = in_sizes[0] / IN_DIM;
    int E = in_sizes[1] / 2;
    int nbScan = (N + 255) / 256;

    __half* ywh;
    cudaGetSymbolAddress((void**)&ywh, g_ywh);

    static cudaStream_t s1 = 0;
    static cudaEvent_t ev_fork = 0, ev_join = 0;
    if (!s1) {
        cudaFuncSetAttribute(gemm1_tc_kernel,
                             cudaFuncAttributeMaxDynamicSharedMemorySize, G1_SMEM);
        cudaStreamCreateWithFlags(&s1, cudaStreamNonBlocking);
        cudaEventCreateWithFlags(&ev_fork, cudaEventDisableTiming);
        cudaEventCreateWithFlags(&ev_join, cudaEventDisableTiming);
    }

    cudaEventRecord(ev_fork, 0);
    cudaStreamWaitEvent(s1, ev_fork, 0);

    csr_fused_kernel<<<NB_FUSED, 256, 0, s1>>>(ei, N, E, nbScan);
    cudaEventRecord(ev_join, s1);

    gemm1_tc_kernel<<<(N + 127) / 128, 256, G1_SMEM>>>(x, W1, ywh, N);

    cudaStreamWaitEvent(0, ev_join, 0);

    tail_fused_kernel<<<NB_FUSED, 256>>>(b1, W2, b2, out, N);
}

// round 17
// speedup vs baseline: 1.6274x; 1.6274x over previous
#include <cuda_runtime.h>
#include <cuda_fp16.h>

#define IN_DIM 128
#define HIDD   128
#define OUTD   40
#define MAXN   50000
#define MAXE   800000
#define NB_FUSED 592   // 4 blocks/SM x 148 SMs, 1024 thr/SM: co-resident

// ---------------- scratch (device globals: allocation-free) ----------------
static __device__ __half g_ywh[MAXN * HIDD];  // fp16: (x @ W1), unscaled
static __device__ __align__(16) __half g_hh[MAXN * HIDD]; // fp16 layer-1 out
static __device__ __half g_owh[MAXN * OUTD];  // fp16: dinv * (h @ W2)
static __device__ int    g_degi[MAXN];
static __device__ float  g_dinv[MAXN];
static __device__ int    g_rs  [MAXN + 1];
static __device__ int    g_cur [MAXN];
static __device__ int    g_col [MAXE];
static __device__ int    g_bsum[(MAXN + 255) / 256];
static __device__ unsigned g_bar_count;       // load-time 0; self-cleaning
static __device__ unsigned g_bar_gen;         // monotonic

// ---------------- helpers ----------------
__device__ __forceinline__ int detect_is64_warp(const int* __restrict__ ei32) {
    int lane = threadIdx.x & 31;
    int v = ei32[1 + 2 * lane];
    unsigned any = __ballot_sync(0xffffffffu, v != 0);
    return any == 0 ? 1 : 0;
}

__device__ __forceinline__ int get_idx(const void* ei, long long pos, int is64) {
    return is64 ? (int)((const long long*)ei)[pos] : ((const int*)ei)[pos];
}

__device__ __forceinline__ unsigned pack_h2(float a, float b) {
    __half2 h = __floats2half2_rn(a, b);
    return *(unsigned*)&h;
}

__device__ __forceinline__ void grid_barrier() {
    __syncthreads();
    if (threadIdx.x == 0) {
        __threadfence();
        unsigned gen = *(volatile unsigned*)&g_bar_gen;
        if (atomicAdd(&g_bar_count, 1u) == (unsigned)gridDim.x - 1u) {
            g_bar_count = 0;
            __threadfence();
            *(volatile unsigned*)&g_bar_gen = gen + 1u;
        } else {
            while (*(volatile unsigned*)&g_bar_gen == gen) __nanosleep(64);
        }
        __threadfence();
    }
    __syncthreads();
}

// ---------------- fused CSR build: deg -> scan -> rs/dinv -> scatter --------
__global__ void __launch_bounds__(256) csr_fused_kernel(const void* __restrict__ ei,
                                                        int N, int E, int nbScan) {
    const int tid = threadIdx.x;
    const int bid = blockIdx.x;
    const int lane = tid & 31, wid = tid >> 5;
    const int is64 = detect_is64_warp((const int*)ei);
    const int stride = gridDim.x * 256;

    for (int e = bid * 256 + tid; e < E; e += stride) {
        int d = get_idx(ei, (long long)E + e, is64);
        atomicAdd(&g_degi[d], 1);
    }
    grid_barrier();

    if (bid < nbScan) {
        int i = bid * 256 + tid;
        int v = (i < N) ? g_degi[i] : 0;
#pragma unroll
        for (int o = 16; o > 0; o >>= 1) v += __shfl_xor_sync(0xffffffffu, v, o);
        __shared__ int ps[8];
        if (lane == 0) ps[wid] = v;
        __syncthreads();
        if (tid == 0) {
            int s = 0;
#pragma unroll
            for (int w = 0; w < 8; w++) s += ps[w];
            g_bsum[bid] = s;
        }
    }
    grid_barrier();

    if (bid == 0) {
        int v = (tid < nbScan) ? g_bsum[tid] : 0;
        __shared__ int ws2[32];
        if (tid < 32) ws2[tid] = 0;
        __syncthreads();
        int x = v;
#pragma unroll
        for (int o = 1; o < 32; o <<= 1) {
            int u = __shfl_up_sync(0xffffffffu, x, o);
            if (lane >= o) x += u;
        }
        if (lane == 31) ws2[wid] = x;
        __syncthreads();
        if (wid == 0) {
            int w = ws2[lane];
#pragma unroll
            for (int o = 1; o < 32; o <<= 1) {
                int u = __shfl_up_sync(0xffffffffu, w, o);
                if (lane >= o) w += u;
            }
            ws2[lane] = w;
        }
        __syncthreads();
        int excl = x - v + (wid > 0 ? ws2[wid - 1] : 0);
        if (tid < nbScan) g_bsum[tid] = excl;
    }
    grid_barrier();

    if (bid < nbScan) {
        int i = bid * 256 + tid;
        int v = (i < N) ? g_degi[i] : 0;
        __shared__ int ws3[32];
        if (tid < 32) ws3[tid] = 0;
        __syncthreads();
        int x = v;
#pragma unroll
        for (int o = 1; o < 32; o <<= 1) {
            int u = __shfl_up_sync(0xffffffffu, x, o);
            if (lane >= o) x += u;
        }
        if (lane == 31) ws3[wid] = x;
        __syncthreads();
        if (wid == 0) {
            int w = ws3[lane];
#pragma unroll
            for (int o = 1; o < 32; o <<= 1) {
                int u = __shfl_up_sync(0xffffffffu, w, o);
                if (lane >= o) w += u;
            }
            ws3[lane] = w;
        }
        __syncthreads();
        int excl = x - v + (wid > 0 ? ws3[wid - 1] : 0) + g_bsum[bid];
        if (i < N) {
            g_rs[i]   = excl;
            g_cur[i]  = excl;
            g_dinv[i] = rsqrtf((float)(v + 1));
            g_degi[i] = 0;
        }
        if (i == 0) g_rs[N] = E;
    }
    grid_barrier();

    for (int e = bid * 256 + tid; e < E; e += stride) {
        int s = get_idx(ei, e, is64);
        int d = get_idx(ei, (long long)E + e, is64);
        int pos = atomicAdd(&g_cur[d], 1);
        g_col[pos] = s;
    }
}

// ---------------- FP16 GEMM1 (256 thr, 8 warps x [32 rows x 64 cols]) -------
#define G1_LDA 68
#define G1_LDB 136
#define G1_SMEM ((128 * G1_LDA + 64 * G1_LDB) * 4)

__global__ void __launch_bounds__(256, 2) gemm1_tc_kernel(const float* __restrict__ A,
                                                          const float* __restrict__ B,
                                                          __half* __restrict__ C, int M) {
    extern __shared__ unsigned sm1[];
    unsigned* As = sm1;
    unsigned* Bs = sm1 + 128 * G1_LDA;

    const int tid  = threadIdx.x;
    const int wid  = tid >> 5;
    const int lane = tid & 31;
    const int g    = lane >> 2;
    const int t    = lane & 3;
    const int wr   = wid & 3;
    const int wn   = wid >> 2;
    const int row0 = blockIdx.x * 128;

    for (int idx = tid; idx < 64 * 128; idx += 256) {
        int kw = idx >> 7, n = idx & 127;
        Bs[kw * G1_LDB + n] = pack_h2(B[(size_t)(2 * kw) * 128 + n],
                                      B[(size_t)(2 * kw + 1) * 128 + n]);
    }
#pragma unroll
    for (int f = 0; f < 16; f++) {
        int l4  = tid + f * 256;
        int row = l4 >> 5;
        int fq  = l4 & 31;
        float4 v = make_float4(0.f, 0.f, 0.f, 0.f);
        if (row0 + row < M)
            v = *(const float4*)(A + (size_t)(row0 + row) * 128 + fq * 4);
        As[row * G1_LDA + fq * 2    ] = pack_h2(v.x, v.y);
        As[row * G1_LDA + fq * 2 + 1] = pack_h2(v.z, v.w);
    }
    __syncthreads();

    float c[2][8][4];
#pragma unroll
    for (int mi = 0; mi < 2; mi++)
#pragma unroll
        for (int j = 0; j < 8; j++)
#pragma unroll
            for (int q = 0; q < 4; q++) c[mi][j][q] = 0.0f;

#pragma unroll
    for (int kh = 0; kh < 8; kh++) {
        unsigned a[2][4];
#pragma unroll
        for (int mi = 0; mi < 2; mi++) {
            int R = wr * 32 + mi * 16;
            a[mi][0] = As[(R + g    ) * G1_LDA + kh * 8 + t    ];
            a[mi][1] = As[(R + 8 + g) * G1_LDA + kh * 8 + t    ];
            a[mi][2] = As[(R + g    ) * G1_LDA + kh * 8 + t + 4];
            a[mi][3] = As[(R + 8 + g) * G1_LDA + kh * 8 + t + 4];
        }
#pragma unroll
        for (int j = 0; j < 8; j++) {
            int n = wn * 64 + j * 8 + g;
            unsigned b0 = Bs[(kh * 8 + t    ) * G1_LDB + n];
            unsigned b1 = Bs[(kh * 8 + t + 4) * G1_LDB + n];
#pragma unroll
            for (int mi = 0; mi < 2; mi++) {
                asm volatile(
                    "mma.sync.aligned.m16n8k16.row.col.f32.f16.f16.f32 "
                    "{%0,%1,%2,%3}, {%4,%5,%6,%7}, {%8,%9}, {%0,%1,%2,%3};"
                    : "+f"(c[mi][j][0]), "+f"(c[mi][j][1]),
                      "+f"(c[mi][j][2]), "+f"(c[mi][j][3])
                    : "r"(a[mi][0]), "r"(a[mi][1]), "r"(a[mi][2]), "r"(a[mi][3]),
                      "r"(b0), "r"(b1));
            }
        }
    }

#pragma unroll
    for (int mi = 0; mi < 2; mi++) {
        int r1 = row0 + wr * 32 + mi * 16 + g;
        int r2 = r1 + 8;
#pragma unroll
        for (int j = 0; j < 8; j++) {
            int n = wn * 64 + j * 8 + t * 2;
            if (r1 < M)
                *(__half2*)(C + (size_t)r1 * 128 + n) =
                    __floats2half2_rn(c[mi][j][0], c[mi][j][1]);
            if (r2 < M)
                *(__half2*)(C + (size_t)r2 * 128 + n) =
                    __floats2half2_rn(c[mi][j][2], c[mi][j][3]);
        }
    }
}

// ---------------- FP16 GEMM2 (R14 best: 256 thr, 8 warps x [16 x 40], BM=128)
#define G2_LDA 68
#define G2_LDB 40

__global__ void __launch_bounds__(256) gemm2_tc_kernel(const __half* __restrict__ A,
                                                       const float* __restrict__ B,
                                                       __half* __restrict__ C, int M) {
    __shared__ unsigned As[128 * G2_LDA];
    __shared__ unsigned Bs[64 * G2_LDB];

    const int tid  = threadIdx.x;
    const int wid  = tid >> 5;
    const int lane = tid & 31;
    const int g    = lane >> 2;
    const int t    = lane & 3;
    const int row0 = blockIdx.x * 128;

    for (int idx = tid; idx < 64 * OUTD; idx += 256) {
        int kw = idx / OUTD, n = idx - kw * OUTD;
        Bs[kw * G2_LDB + n] = pack_h2(B[(size_t)(2 * kw) * OUTD + n],
                                      B[(size_t)(2 * kw + 1) * OUTD + n]);
    }
#pragma unroll
    for (int f = 0; f < 8; f++) {
        int idx = tid + f * 256;           // 2048 uint4
        int row = idx >> 4;
        int c4  = idx & 15;
        uint4 v = make_uint4(0u, 0u, 0u, 0u);
        if (row0 + row < M)
            v = *(const uint4*)(A + (size_t)(row0 + row) * 128 + c4 * 8);
        *(uint4*)(As + row * G2_LDA + c4 * 4) = v;
    }
    __syncthreads();

    float c[5][4];
#pragma unroll
    for (int j = 0; j < 5; j++)
#pragma unroll
        for (int q = 0; q < 4; q++) c[j][q] = 0.0f;

#pragma unroll
    for (int kh = 0; kh < 8; kh++) {
        int R = wid * 16;
        unsigned a0 = As[(R + g    ) * G2_LDA + kh * 8 + t    ];
        unsigned a1 = As[(R + 8 + g) * G2_LDA + kh * 8 + t    ];
        unsigned a2 = As[(R + g    ) * G2_LDA + kh * 8 + t + 4];
        unsigned a3 = As[(R + 8 + g) * G2_LDA + kh * 8 + t + 4];
#pragma unroll
        for (int j = 0; j < 5; j++) {
            int n = j * 8 + g;
            unsigned b0 = Bs[(kh * 8 + t    ) * G2_LDB + n];
            unsigned b1 = Bs[(kh * 8 + t + 4) * G2_LDB + n];
            asm volatile(
                "mma.sync.aligned.m16n8k16.row.col.f32.f16.f16.f32 "
                "{%0,%1,%2,%3}, {%4,%5,%6,%7}, {%8,%9}, {%0,%1,%2,%3};"
                : "+f"(c[j][0]), "+f"(c[j][1]), "+f"(c[j][2]), "+f"(c[j][3])
                : "r"(a0), "r"(a1), "r"(a2), "r"(a3), "r"(b0), "r"(b1));
        }
    }

    int r1 = row0 + wid * 16 + g;
    int r2 = r1 + 8;
    float d1 = (r1 < M) ? g_dinv[r1] : 0.0f;
    float d2 = (r2 < M) ? g_dinv[r2] : 0.0f;
#pragma unroll
    for (int j = 0; j < 5; j++) {
        int n = j * 8 + t * 2;
        if (r1 < M)
            *(__half2*)(C + (size_t)r1 * OUTD + n) = __floats2half2_rn(c[j][0] * d1, c[j][1] * d1);
        if (r2 < M)
            *(__half2*)(C + (size_t)r2 * OUTD + n) = __floats2half2_rn(c[j][2] * d2, c[j][3] * d2);
    }
}

// ---------------- layer-1 aggregation (warp/node, dinv folded at gather) ----
__global__ void __launch_bounds__(256) agg1_kernel(const float* __restrict__ b1, int N) {
    int warp = (blockIdx.x * blockDim.x + threadIdx.x) >> 5;
    int lane = threadIdx.x & 31;
    if (warp >= N) return;
    int d = warp;
    const __half* __restrict__ yw = g_ywh;
    float di = g_dinv[d];

    uint2 u = *(const uint2*)(yw + (size_t)d * 128 + lane * 4);
    float2 f0 = __half22float2(*(__half2*)&u.x);
    float2 f1 = __half22float2(*(__half2*)&u.y);
    float4 acc = make_float4(f0.x * di, f0.y * di, f1.x * di, f1.y * di);

    int s0 = g_rs[d], s1 = g_rs[d + 1];
    for (int base = s0; base < s1; base += 32) {
        int n = s1 - base; if (n > 32) n = 32;
        int c = (lane < n) ? g_col[base + lane] : 0;
        float dv = (lane < n) ? g_dinv[c] : 0.0f;
#pragma unroll 4
        for (int j = 0; j < n; j++) {
            int s = __shfl_sync(0xffffffffu, c, j);
            float w = __shfl_sync(0xffffffffu, dv, j);
            uint2 v = *(const uint2*)(yw + (size_t)s * 128 + lane * 4);
            float2 a = __half22float2(*(__half2*)&v.x);
            float2 b = __half22float2(*(__half2*)&v.y);
            acc.x = fmaf(a.x, w, acc.x);
            acc.y = fmaf(a.y, w, acc.y);
            acc.z = fmaf(b.x, w, acc.z);
            acc.w = fmaf(b.y, w, acc.w);
        }
    }
    float4 bb = *(const float4*)(b1 + lane * 4);
    uint2 st;
    st.x = pack_h2(fmaxf(acc.x * di + bb.x, 0.0f), fmaxf(acc.y * di + bb.y, 0.0f));
    st.y = pack_h2(fmaxf(acc.z * di + bb.z, 0.0f), fmaxf(acc.w * di + bb.w, 0.0f));
    *(uint2*)(g_hh + (size_t)d * 128 + lane * 4) = st;
}

// ---------------- layer-2 aggregation + softmax (warp/node, dual-neighbor) --
__global__ void __launch_bounds__(256) agg2_kernel(float* __restrict__ out,
                                                   const float* __restrict__ b2, int N) {
    int warp = (blockIdx.x * blockDim.x + threadIdx.x) >> 5;
    int lane = threadIdx.x & 31;
    if (warp >= N) return;
    int d = warp;
    const __half* __restrict__ ow = g_owh;

    int grp = lane >> 4;
    int sub = lane & 15;
    bool act = (sub < 10);

    float4 acc = make_float4(0.f, 0.f, 0.f, 0.f);
    if (lane < 10) {
        uint2 u = *(const uint2*)(ow + (size_t)d * OUTD + lane * 4);
        float2 f0 = __half22float2(*(__half2*)&u.x);
        float2 f1 = __half22float2(*(__half2*)&u.y);
        acc = make_float4(f0.x, f0.y, f1.x, f1.y);
    }

    int s0 = g_rs[d], s1 = g_rs[d + 1];
    for (int base = s0; base < s1; base += 32) {
        int n = s1 - base; if (n > 32) n = 32;
        int c = (lane < n) ? g_col[base + lane] : 0;
        for (int j = 0; j < n; j += 2) {
            int idx = j + grp;
            int s = __shfl_sync(0xffffffffu, c, idx & 31);
            if (act && idx < n) {
                uint2 v = *(const uint2*)(ow + (size_t)s * OUTD + sub * 4);
                float2 a = __half22float2(*(__half2*)&v.x);
                float2 b = __half22float2(*(__half2*)&v.y);
                acc.x += a.x; acc.y += a.y; acc.z += b.x; acc.w += b.y;
            }
        }
    }

    acc.x += __shfl_xor_sync(0xffffffffu, acc.x, 16);
    acc.y += __shfl_xor_sync(0xffffffffu, acc.y, 16);
    acc.z += __shfl_xor_sync(0xffffffffu, acc.z, 16);
    acc.w += __shfl_xor_sync(0xffffffffu, acc.w, 16);

    float di = g_dinv[d];
    float4 l = make_float4(-1e30f, -1e30f, -1e30f, -1e30f);
    if (lane < 10) {
        float4 bb = *(const float4*)(b2 + lane * 4);
        l.x = acc.x * di + bb.x;
        l.y = acc.y * di + bb.y;
        l.z = acc.z * di + bb.z;
        l.w = acc.w * di + bb.w;
    }
    float m = fmaxf(fmaxf(l.x, l.y), fmaxf(l.z, l.w));
#pragma unroll
    for (int o = 16; o > 0; o >>= 1)
        m = fmaxf(m, __shfl_xor_sync(0xffffffffu, m, o));
    float4 e;
    e.x = __expf(l.x - m); e.y = __expf(l.y - m);
    e.z = __expf(l.z - m); e.w = __expf(l.w - m);
    float s = (lane < 10) ? (e.x + e.y + e.z + e.w) : 0.0f;
#pragma unroll
    for (int o = 16; o > 0; o >>= 1)
        s += __shfl_xor_sync(0xffffffffu, s, o);
    float inv = 1.0f / s;
    if (lane < 10) {
        float4 w;
        w.x = e.x * inv; w.y = e.y * inv; w.z = e.z * inv; w.w = e.w * inv;
        *(float4*)(out + (size_t)d * OUTD + lane * 4) = w;
    }
}

// ---------------- launch (csr_fused || gemm1, then chain) ----------------
extern "C" void kernel_launch(void* const* d_in, const int* in_sizes, int n_in,
                              void* d_out, int out_size) {
    const float* x  = (const float*)d_in[0];
    const void*  ei = d_in[1];
    const float* W1 = (const float*)d_in[2];
    const float* b1 = (const float*)d_in[3];
    const float* W2 = (const float*)d_in[4];
    const float* b2 = (const float*)d_in[5];
    float* out = (float*)d_out;

    int N = in_sizes[0] / IN_DIM;
    int E = in_sizes[1] / 2;
    int nbScan = (N + 255) / 256;

    __half *ywh, *hh, *owh;
    cudaGetSymbolAddress((void**)&ywh, g_ywh);
    cudaGetSymbolAddress((void**)&hh,  g_hh);
    cudaGetSymbolAddress((void**)&owh, g_owh);

    static cudaStream_t s1 = 0;
    static cudaEvent_t ev_fork = 0, ev_join = 0;
    if (!s1) {
        cudaFuncSetAttribute(gemm1_tc_kernel,
                             cudaFuncAttributeMaxDynamicSharedMemorySize, G1_SMEM);
        cudaStreamCreateWithFlags(&s1, cudaStreamNonBlocking);
        cudaEventCreateWithFlags(&ev_fork, cudaEventDisableTiming);
        cudaEventCreateWithFlags(&ev_join, cudaEventDisableTiming);
    }

    cudaEventRecord(ev_fork, 0);
    cudaStreamWaitEvent(s1, ev_fork, 0);

    csr_fused_kernel<<<NB_FUSED, 256, 0, s1>>>(ei, N, E, nbScan);
    cudaEventRecord(ev_join, s1);

    gemm1_tc_kernel<<<(N + 127) / 128, 256, G1_SMEM>>>(x, W1, ywh, N);

    cudaStreamWaitEvent(0, ev_join, 0);

    agg1_kernel<<<(N * 32 + 255) / 256, 256>>>(b1, N);
    gemm2_tc_kernel<<<(N + 127) / 128, 256>>>(hh, W2, owh, N);
    agg2_kernel<<<(N * 32 + 255) / 256, 256>>>(out, b2, N);
}